// round 16
// baseline (speedup 1.0000x reference)
#include <cuda_runtime.h>
#include <math.h>
#include <stdint.h>

#define S_LEN 2048
#define DHEAD 128
#define NHEAD 8
#define NB 2
#define WIN 511
#define QK_SCALE 0.08838834764831845f   // 1/sqrt(128)
#define LOG2E 1.4426950408889634f
#define QK_SL2E (QK_SCALE * LOG2E)

// Projected Q/K/V scratch: [B][H][S][D] fp32. Q,K stored with d permuted
// within each 8-block: d -> (d&~7)|((d&3)<<1)|((d>>2)&1). V natural order.
__device__ float g_Qp[NB*NHEAD*S_LEN*DHEAD];
__device__ float g_Kp[NB*NHEAD*S_LEN*DHEAD];
__device__ float g_Vp[NB*NHEAD*S_LEN*DHEAD];

// ---------------------------------------------------------------------------
// helpers
// ---------------------------------------------------------------------------
__device__ __forceinline__ uint32_t tf32r(float x) {
    uint32_t r; asm("cvt.rn.tf32.f32 %0, %1;" : "=r"(r) : "f"(x)); return r;
}
__device__ __forceinline__ void mma8(float* c, const uint32_t* a, uint32_t b0, uint32_t b1) {
    asm("mma.sync.aligned.m16n8k8.row.col.f32.tf32.tf32.f32 "
        "{%0,%1,%2,%3}, {%4,%5,%6,%7}, {%8,%9}, {%0,%1,%2,%3};"
        : "+f"(c[0]), "+f"(c[1]), "+f"(c[2]), "+f"(c[3])
        : "r"(a[0]), "r"(a[1]), "r"(a[2]), "r"(a[3]), "r"(b0), "r"(b1));
}
__device__ __forceinline__ uint4 cvt4(float4 a) {
    return make_uint4(tf32r(a.x), tf32r(a.y), tf32r(a.z), tf32r(a.w));
}
__device__ __forceinline__ void cpasync16(uint32_t dst, const void* src) {
    asm volatile("cp.async.cg.shared.global [%0], [%1], 16;" :: "r"(dst), "l"(src));
}
#define CP_COMMIT() asm volatile("cp.async.commit_group;" ::: "memory")
#define CP_WAIT0()  asm volatile("cp.async.wait_group 0;"  ::: "memory")
__device__ __forceinline__ int permd(int d) {
    return (d & ~7) | ((d & 3) << 1) | ((d >> 2) & 1);
}

// ---------------------------------------------------------------------------
// Projection GEMM via tf32 mma (unchanged from round 15).
// ---------------------------------------------------------------------------
#define PX_STR 132
#define PW_STR 136
#define WS_SIZE 17648

__global__ __launch_bounds__(512, 1) void proj_mma(
    const float* __restrict__ q, const float* __restrict__ k, const float* __restrict__ v,
    const float* __restrict__ Wq, const float* __restrict__ Wk, const float* __restrict__ Wv)
{
    extern __shared__ float sm[];
    float* Xs = sm;                    // [128][132]  row-major (m,k), raw fp32
    float* Ws = sm + 128 * PX_STR;     // skewed n-major, k-slots permuted, tf32
    uint32_t smb = (uint32_t)__cvta_generic_to_shared(sm);

    const float *X, *W; float* O; bool perm;
    if (blockIdx.z == 0)      { X = q; W = Wq; O = g_Qp; perm = true;  }
    else if (blockIdx.z == 1) { X = k; W = Wk; O = g_Kp; perm = true;  }
    else                      { X = v; W = Wv; O = g_Vp; perm = false; }

    int m0 = blockIdx.x << 7;
    int n0 = blockIdx.y << 7;          // == head * 128
    int tid = threadIdx.x;
    int lane = tid & 31, w = tid >> 5, g = lane >> 2, t = lane & 3;
    int p = w >> 1, half = w & 1;

    {
        int r = tid >> 3, c0 = (tid & 7) << 4;
        #pragma unroll
        for (int hv = 0; hv < 2; hv++) {
            int rr = r + hv * 64;
            const float* src = X + (size_t)(m0 + rr) * DHEAD + c0;
            uint32_t dst = smb + (uint32_t)(rr * PX_STR + c0) * 4u;
            #pragma unroll
            for (int i = 0; i < 4; i++) cpasync16(dst + i * 16, src + i * 4);
        }
    }
    CP_COMMIT();

    {
        int kk = tid >> 2, kp = permd(kk);
        const float* wsrc = W + (size_t)kk * 1024 + n0;
        #pragma unroll
        for (int j = 0; j < 8; j++) {
            int n = (tid & 3) * 4 + j * 16;
            float4 a = *(const float4*)(wsrc + n);
            float vv[4] = {a.x, a.y, a.z, a.w};
            float* wd = Ws + ((n >> 2) << 3) + kp;
            #pragma unroll
            for (int e = 0; e < 4; e++)
                wd[(n + e) * PW_STR] = __uint_as_float(tf32r(vv[e]));
        }
    }
    CP_WAIT0();
    __syncthreads();

    uint32_t qa[16][4];
    {
        const float* ab = Xs + (16 * p + g) * PX_STR + t;
        #pragma unroll
        for (int ks = 0; ks < 16; ks++) {
            qa[ks][0] = tf32r(ab[ks * 8]);
            qa[ks][1] = tf32r(ab[8 * PX_STR + ks * 8]);
            qa[ks][2] = tf32r(ab[ks * 8 + 4]);
            qa[ks][3] = tf32r(ab[8 * PX_STR + ks * 8 + 4]);
        }
    }

    float acc[8][4];
    #pragma unroll
    for (int nb = 0; nb < 8; nb++)
        #pragma unroll
        for (int e = 0; e < 4; e++) acc[nb][e] = 0.f;

    int nbo = half << 3;
    #pragma unroll
    for (int nb = 0; nb < 8; nb++) {
        int row = (nbo + nb) * 8 + g;
        const float* wrow = Ws + row * PW_STR + ((row >> 2) << 3) + 2 * t;
        #pragma unroll
        for (int ks = 0; ks < 16; ks++) {
            uint2 bu = *(const uint2*)&wrow[ks * 8];
            mma8(acc[nb], qa[ks], bu.x, bu.y);
        }
    }

    int m = m0 + 16 * p + g;
    int b = m >> 11, s = m & 2047;
    int hh = n0 >> 7, dbase = half << 6;
    float* dst = O + ((size_t)((b * NHEAD + hh) * S_LEN + s) * DHEAD);
    if (perm) {
        #pragma unroll
        for (int nb = 0; nb < 8; nb++) {
            int d0 = dbase + nb * 8 + 2 * t, d1 = d0 + 1;
            int p0 = permd(d0), p1 = permd(d1);
            dst[p0] = acc[nb][0];
            dst[p1] = acc[nb][1];
            dst[8 * DHEAD + p0] = acc[nb][2];
            dst[8 * DHEAD + p1] = acc[nb][3];
        }
    } else {
        #pragma unroll
        for (int nb = 0; nb < 8; nb++) {
            int d = dbase + nb * 8 + 2 * t;
            *(float2*)(dst + d) = make_float2(acc[nb][0], acc[nb][1]);
            *(float2*)(dst + 8 * DHEAD + d) = make_float2(acc[nb][2], acc[nb][3]);
        }
    }
}

// ---------------------------------------------------------------------------
// Windowed attention via tf32 mma. CTA = 64 queries x (head, batch),
// 256 threads = 8 warps = 4 warp-PAIRS; pair p owns query rows 16p..16p+15.
//   even warp of pair: QK keys 0-31,  PV d 0-63
//   odd  warp of pair: QK keys 32-63, PV d 64-127
// SINGLE-buffered 64-key K/V tiles (cp.async); Q A-frags via direct LDG
// (no Q staging) -> smem 89.6KB -> 2 CTAs/SM, anti-phased latency hiding.
// ---------------------------------------------------------------------------
#define KSTR 136
#define VSTR 136
#define PSTR 68
// smem float offsets
#define SK   0                       // 64x136
#define SV   (64*KSTR)               // 8704
#define SP   (2*64*KSTR)             // 17408: 4 pairs x 16x68
#define SEMB (SP + 4*16*PSTR)        // 21760
#define SLS  (SEMB + 512)            // 22272: 4 pairs x 32
#define STOT (SLS + 128)             // 22400 floats = 89600 B

__device__ __forceinline__ void cp_kv256(const float* __restrict__ Kh,
                                         const float* __restrict__ Vh, int row0,
                                         uint32_t smb, int tid) {
    int r = tid >> 2, c0 = (tid & 3) << 5;
    const float* ks = Kh + (size_t)(row0 + r) * DHEAD + c0;
    const float* vs = Vh + (size_t)(row0 + r) * DHEAD + c0;
    uint32_t kd = smb + (uint32_t)(SK + r * KSTR + c0) * 4u;
    uint32_t vd = smb + (uint32_t)(SV + r * VSTR + c0) * 4u;
    #pragma unroll
    for (int i = 0; i < 8; i++) {
        cpasync16(kd + i * 16, ks + i * 4);
        cpasync16(vd + i * 16, vs + i * 4);
    }
}

// exp(score*QK_SCALE + emb) as 2^(...) with a degree-5 poly (no MUFU).
__device__ __forceinline__ float pcalc(float a, int d, const float* __restrict__ embS) {
    if (d < 0) return 0.f;                      // causal+rpe masked
    unsigned u = (unsigned)(d - 1);
    float bias = (u < 511u) ? embS[u] : -2e9f;  // out of window / diagonal
    float y = fmaf(a, QK_SL2E, bias);
    y = fmaxf(y, -126.f);
    float rr = y + 12582912.f;                  // 1.5*2^23 round-to-int magic
    float f = y - (rr - 12582912.f);            // f in [-0.5, 0.5]
    int   n = __float_as_int(rr) << 23;
    float pp =         1.8775767e-3f;
    pp = fmaf(pp, f,   8.9893397e-3f);
    pp = fmaf(pp, f,   5.5826318e-2f);
    pp = fmaf(pp, f,   2.4015361e-1f);
    pp = fmaf(pp, f,   6.9315308e-1f);
    pp = fmaf(pp, f,   1.0f);
    return __int_as_float(__float_as_int(pp) + n);
}

__global__ __launch_bounds__(256, 2) void attn_mma(
    const float* __restrict__ emb, float* __restrict__ out)
{
    extern __shared__ float sm[];
    float* embS = sm + SEMB;
    uint32_t smb = (uint32_t)__cvta_generic_to_shared(sm);

    int tid = threadIdx.x;
    int lane = tid & 31, w = tid >> 5, g = lane >> 2, t = lane & 3;
    int p = w >> 1, half = w & 1;
    int qt = 31 - blockIdx.x;            // heavy-first
    int qs = qt << 6, h = blockIdx.y, b = blockIdx.z;
    size_t ho = (size_t)(b * NHEAD + h) * S_LEN * DHEAD;
    const float* Qh = g_Qp + ho;
    const float* Kh = g_Kp + ho;
    const float* Vh = g_Vp + ho;

    int kt_lo = (qs >= WIN) ? ((qs - WIN) >> 6) : 0;
    int T = qt - kt_lo + 1;              // kt_hi == qt for 64-row tiles

    // prefetch tile 0 (overlaps emb + Q frag LDGs)
    cp_kv256(Kh, Vh, kt_lo << 6, smb, tid);
    CP_COMMIT();

    for (int i = tid; i < 512; i += 256) embS[i] = emb[i] * LOG2E;

    int r_lo = qs + 16 * p, r_hi = r_lo + 15;
    int r0 = r_lo + g;

    // Q A-frags via direct LDG from d-permuted g_Qp (one-time)
    uint32_t qa[16][4];
    {
        const float* qp = Qh + (size_t)r0 * DHEAD + 2 * t;
        #pragma unroll
        for (int ks = 0; ks < 16; ks++) {
            float2 f0 = *(const float2*)(qp + ks * 8);
            float2 f1 = *(const float2*)(qp + 8 * DHEAD + ks * 8);
            qa[ks][0] = tf32r(f0.x); qa[ks][1] = tf32r(f1.x);
            qa[ks][2] = tf32r(f0.y); qa[ks][3] = tf32r(f1.y);
        }
    }
    CP_WAIT0();
    __syncthreads();    // tile-0 K/V + emb visible

    float* Ps = sm + SP + p * (16 * PSTR);   // per-PAIR P buffer [16][68]

    float oacc[8][4];
    #pragma unroll
    for (int nb = 0; nb < 8; nb++)
        #pragma unroll
        for (int e = 0; e < 4; e++) oacc[nb][e] = 0.f;
    float sum0 = 0.f, sum1 = 0.f;

    int nbq = half << 2;     // QK key-block offset (nb 0-3 / 4-7)
    int dvo = half << 6;     // PV d offset (0 / 64)
    const float* kb = sm + SK;
    const float* vb = sm + SV;

    for (int i = 0; i < T; i++) {
        int ks0 = (kt_lo + i) << 6;
        bool active = (ks0 <= r_hi) && (ks0 + 63 >= r_lo - WIN);

        if (active) {
            // --- QK: S[16 x 32] (this warp's key half) ---
            float acc[4][4];
            #pragma unroll
            for (int nb = 0; nb < 4; nb++)
                #pragma unroll
                for (int e = 0; e < 4; e++) acc[nb][e] = 0.f;
            #pragma unroll
            for (int ks = 0; ks < 16; ks++) {
                #pragma unroll
                for (int nb = 0; nb < 4; nb++) {
                    uint2 bu = *(const uint2*)&kb[((nbq + nb) * 8 + g) * KSTR + ks * 8 + 2 * t];
                    mma8(acc[nb], qa[ks], bu.x, bu.y);
                }
            }

            // --- softmax (FMA-pipe exp2) + P store into pair buffer ---
            #pragma unroll
            for (int nb = 0; nb < 4; nb++) {
                int j0 = ks0 + (nbq + nb) * 8 + 2 * t;
                int d00 = r0 - j0;
                float p00 = pcalc(acc[nb][0], d00,     embS);
                float p01 = pcalc(acc[nb][1], d00 - 1, embS);
                float p10 = pcalc(acc[nb][2], d00 + 8, embS);
                float p11 = pcalc(acc[nb][3], d00 + 7, embS);
                sum0 += p00 + p01;
                sum1 += p10 + p11;
                int c = (nbq + nb) * 8 + 2 * t;
                *(uint2*)&Ps[g * PSTR + c] = make_uint2(tf32r(p00), tf32r(p01));
                *(uint2*)&Ps[(g + 8) * PSTR + c] = make_uint2(tf32r(p10), tf32r(p11));
            }
            asm volatile("bar.sync %0, %1;" :: "r"(p + 1), "r"(64) : "memory");

            // --- PV: O[16 x 64] (this warp's d half) over all 64 keys ---
            #pragma unroll
            for (int ks = 0; ks < 8; ks++) {
                uint32_t pa[4];
                pa[0] = __float_as_uint(Ps[g * PSTR + ks * 8 + t]);
                pa[1] = __float_as_uint(Ps[(g + 8) * PSTR + ks * 8 + t]);
                pa[2] = __float_as_uint(Ps[g * PSTR + ks * 8 + t + 4]);
                pa[3] = __float_as_uint(Ps[(g + 8) * PSTR + ks * 8 + t + 4]);
                const float* bv = vb + (ks * 8 + t) * VSTR + dvo + g;
                #pragma unroll
                for (int nb = 0; nb < 8; nb++) {
                    uint32_t b0 = __float_as_uint(bv[nb * 8]);
                    uint32_t b1 = __float_as_uint(bv[4 * VSTR + nb * 8]);
                    mma8(oacc[nb], pa, b0, b1);
                }
            }
        }

        // single-buffer reload for next tile (sibling CTA hides latency)
        if (i + 1 < T) {
            __syncthreads();                       // everyone done with tile i
            cp_kv256(Kh, Vh, (kt_lo + i + 1) << 6, smb, tid);
            CP_COMMIT(); CP_WAIT0();
            __syncthreads();                       // tile i+1 ready
        }
    }

    // row sums: quad-reduce then combine the two key-halves (pair-local)
    sum0 += __shfl_xor_sync(0xffffffffu, sum0, 1);
    sum0 += __shfl_xor_sync(0xffffffffu, sum0, 2);
    sum1 += __shfl_xor_sync(0xffffffffu, sum1, 1);
    sum1 += __shfl_xor_sync(0xffffffffu, sum1, 2);
    float* ls = sm + SLS;
    if (t == 0) {
        ls[(p * 2 + half) * 16 + g] = sum0;
        ls[(p * 2 + half) * 16 + g + 8] = sum1;
    }
    asm volatile("bar.sync %0, %1;" :: "r"(p + 1), "r"(64) : "memory");
    float linv0 = 1.f / (ls[p * 32 + g] + ls[p * 32 + 16 + g]);
    float linv1 = 1.f / (ls[p * 32 + g + 8] + ls[p * 32 + 16 + g + 8]);

    // epilogue: out[b][s][h*128+d]; row 0 (fully masked) = V[0]
    float* dst0 = out + ((size_t)(b * S_LEN + r0) * (NHEAD * DHEAD)) + h * DHEAD + dvo + 2 * t;
    #pragma unroll
    for (int nb = 0; nb < 8; nb++) {
        float2 v0;
        if (r0 == 0) v0 = make_float2(Vh[dvo + nb * 8 + 2 * t], Vh[dvo + nb * 8 + 2 * t + 1]);
        else         v0 = make_float2(oacc[nb][0] * linv0, oacc[nb][1] * linv0);
        *(float2*)(dst0 + nb * 8) = v0;
        *(float2*)(dst0 + 8 * (NHEAD * DHEAD) + nb * 8) =
            make_float2(oacc[nb][2] * linv1, oacc[nb][3] * linv1);
    }
}

extern "C" void kernel_launch(void* const* d_in, const int* in_sizes, int n_in,
                              void* d_out, int out_size)
{
    (void)in_sizes; (void)n_in; (void)out_size;
    const float* q   = (const float*)d_in[0];
    const float* k   = (const float*)d_in[1];
    const float* v   = (const float*)d_in[2];
    const float* Wq  = (const float*)d_in[3];
    const float* Wk  = (const float*)d_in[4];
    const float* Wv  = (const float*)d_in[5];
    const float* emb = (const float*)d_in[6];
    float* out = (float*)d_out;

    int proj_smem = (128 * PX_STR + WS_SIZE) * 4;
    cudaFuncSetAttribute(proj_mma, cudaFuncAttributeMaxDynamicSharedMemorySize, proj_smem);
    cudaFuncSetAttribute(attn_mma, cudaFuncAttributeMaxDynamicSharedMemorySize, STOT * 4);

    proj_mma<<<dim3(32, 8, 3), 512, proj_smem>>>(q, k, v, Wq, Wk, Wv);
    attn_mma<<<dim3(32, NHEAD, NB), 256, STOT * 4>>>(emb, out);
}